// round 16
// baseline (speedup 1.0000x reference)
#include <cuda_runtime.h>
#include <cuda_bf16.h>
#include <cstdint>

#define T_STEPS 16
#define BATCH   16384
#define DIN     64
#define DH      256
#define DMID    64
#define DOUT    4
#define NTH     512
#define GRID    148
#define NBIG    136             // blocks with 7 m-tiles (rest have 6)

// SMEM layout (bytes). A region kept 8-tile sized (max usage 7) -> no OOB.
#define OFF_A   2560
#define AREG    81920           // 8 mt * 20 ks * 512B
#define OFF_AL  (OFF_A + AREG)
#define OFF_B   (OFF_AL + AREG)
#define OFF_MID (OFF_B + 30720)  // aliases upper B space (used post-h2o)
#define SMEM_TOTAL (OFF_B + 65536)   // 231936

// Weights in MMA-fragment order (bf16 hi/lo). B: [ks 0..19][nt 0..31][128 bf16]
__device__ __nv_bfloat16 g_Bhi[20*32*128];
__device__ __nv_bfloat16 g_Blo[20*32*128];
__device__ __nv_bfloat16 g_Ohi[16*8*128];
__device__ __nv_bfloat16 g_Olo[16*8*128];

__device__ __forceinline__ void split2(float a, float b, uint32_t& hi, uint32_t& lo){
    __nv_bfloat16 ha=__float2bfloat16(a), hb=__float2bfloat16(b);
    float ra=a-__bfloat162float(ha), rb=b-__bfloat162float(hb);
    __nv_bfloat16 la=__float2bfloat16(ra), lb=__float2bfloat16(rb);
    hi = ((uint32_t)(*(uint16_t*)&hb) << 16) | *(uint16_t*)&ha;
    lo = ((uint32_t)(*(uint16_t*)&lb) << 16) | *(uint16_t*)&la;
}
__device__ __forceinline__ void cp16(uint32_t d, const void* s){
    asm volatile("cp.async.cg.shared.global [%0], [%1], 16;"::"r"(d),"l"(s));
}
#define CP_COMMIT() asm volatile("cp.async.commit_group;":::"memory")
#define CP_WAIT1()  asm volatile("cp.async.wait_group 1;":::"memory")
#define CP_WAIT0()  asm volatile("cp.async.wait_group 0;":::"memory")

__device__ __forceinline__ void mma16816(float* c, uint4 a, uint2 b){
    asm("mma.sync.aligned.m16n8k16.row.col.f32.bf16.bf16.f32 "
        "{%0,%1,%2,%3},{%4,%5,%6,%7},{%8,%9},{%0,%1,%2,%3};"
        : "+f"(c[0]),"+f"(c[1]),"+f"(c[2]),"+f"(c[3])
        : "r"(a.x),"r"(a.y),"r"(a.z),"r"(a.w),"r"(b.x),"r"(b.y));
}
__device__ __forceinline__ float tanh_fast(float v){
    float e=__expf(2.0f*v); return 1.0f-__fdividef(2.0f,e+1.0f);
}

// ---- prep: split weights to bf16 hi/lo in fragment order ----
__global__ void prep(const float* __restrict__ Wi, const float* __restrict__ Wh,
                     const float* __restrict__ Wo){
    int i=blockIdx.x*blockDim.x+threadIdx.x;
    if(i < 256*320){
        int j=i/320, k=i%320;
        float v=(k<DIN)? Wi[j*DIN+k] : Wh[j*DH+(k-DIN)];
        __nv_bfloat16 h=__float2bfloat16(v);
        __nv_bfloat16 l=__float2bfloat16(v-__bfloat162float(h));
        uint32_t a=((k>>4)*32+(j>>3))*128 + ((j&7)*4+((k&7)>>1))*4
                 + ((k&15)>>3)*2 + (k&1);
        g_Bhi[a]=h; g_Blo[a]=l;
    } else if(i < 256*320 + 64*256){
        int i2=i-256*320, j=i2/256, k=i2%256;
        float v=Wo[j*DH+k];
        __nv_bfloat16 h=__float2bfloat16(v);
        __nv_bfloat16 l=__float2bfloat16(v-__bfloat162float(h));
        uint32_t a=((k>>4)*8+(j>>3))*128 + ((j&7)*4+((k&7)>>1))*4
                 + ((k&15)>>3)*2 + (k&1);
        g_Ohi[a]=h; g_Olo[a]=l;
    }
}

// ------------------------------- main kernel -------------------------------
__global__ void __launch_bounds__(NTH,1)
rnn_mma(const float* __restrict__ x,     const float* __restrict__ hc1,
        const float* __restrict__ b_i2h, const float* __restrict__ b_h2h,
        const float* __restrict__ b_h2o, const float* __restrict__ W_fc,
        const float* __restrict__ b_fc,
        float* __restrict__ out_seq,     float* __restrict__ h_final)
{
    extern __shared__ __align__(128) char sm[];
    float* cs=(float*)sm;                       // [0,256) bias, [256,320) b_h2o,
    char* Ahi=sm+OFF_A; char* Alo=sm+OFF_AL;    // [320,324) b_fc, [324,580) W_fc
    char* Bb =sm+OFF_B;
    const int tid=threadIdx.x, lane=tid&31, w=tid>>5;
    const int mtp=w>>2, ncg=w&3;
    const int bx=blockIdx.x;
    const int MT=(bx<NBIG)?7:6;
    const int rowbase=16*(6*bx+((bx<NBIG)?bx:NBIG));
    const int nrows=MT*16;
    const bool t0v=(2*mtp  )<MT;
    const bool t1v=(2*mtp+1)<MT;
    const uint32_t sbB=(uint32_t)__cvta_generic_to_shared(Bb);

    if(tid<DH)   cs[tid]    =b_i2h[tid]+b_h2h[tid];
    if(tid<DMID) cs[256+tid]=b_h2o[tid];
    if(tid<DOUT) cs[320+tid]=b_fc[tid];
    if(tid<256)  cs[324+tid]=W_fc[tid];

    // hc1 -> A frag h-region (ks 4..19), rows guarded
    #pragma unroll 4
    for(int i=0;i<32;++i){
        int wi=tid+NTH*i;                       // [0,16384)
        int mt=wi>>11, ks=(wi>>7)&15, ln=(wi>>2)&31, rg=wi&3;
        int row=mt*16+(rg&1)*8+(ln>>2);
        if(row>=nrows) continue;
        int k  =ks*16+(rg>>1)*8+(ln&3)*2;
        float2 v=*(const float2*)&hc1[(size_t)(rowbase+row)*DH+k];
        uint32_t hw,lw; split2(v.x,v.y,hw,lw);
        uint32_t off=(uint32_t)((mt*20+4+ks)*512+ln*16+rg*4);
        *(uint32_t*)(Ahi+off)=hw; *(uint32_t*)(Alo+off)=lw;
    }

    for(int t=0;t<T_STEPS;++t){
        // ---- stage x_t: linear -> Bb (guarded), convert to A frags ks0..3 --
        {
            const float* xp=x+((size_t)t*BATCH+rowbase)*DIN;
            #pragma unroll
            for(int i=0;i<4;++i){
                int e=tid+NTH*i;                // float4 idx, row=e>>4
                if((e>>4)<nrows) cp16(sbB+(uint32_t)(e*16), xp+e*4);
            }
            CP_COMMIT(); CP_WAIT0(); __syncthreads();
            const float* xs=(const float*)Bb;
            #pragma unroll
            for(int i=0;i<8;++i){
                int wi=tid+NTH*i;               // [0,4096)
                int mt=wi>>9, ks=(wi>>7)&3, ln=(wi>>2)&31, rg=wi&3;
                int row=mt*16+(rg&1)*8+(ln>>2);
                int k  =ks*16+(rg>>1)*8+(ln&3)*2;
                float2 v=*(const float2*)&xs[row*DIN+k];
                uint32_t hw,lw; split2(v.x,v.y,hw,lw);
                uint32_t off=(uint32_t)((mt*20+ks)*512+ln*16+rg*4);
                *(uint32_t*)(Ahi+off)=hw; *(uint32_t*)(Alo+off)=lw;
            }
            __syncthreads();
        }

        // ---- main GEMM: C[rows x 256] over K=320, bf16x3 in 2 streamed passes
        float acc[16][4];
        #pragma unroll
        for(int nt=0;nt<8;++nt){
            int col=ncg*64+nt*8+(lane&3)*2;
            float b0=cs[col], b1=cs[col+1];
            acc[nt][0]=b0; acc[nt][1]=b1; acc[nt][2]=b0; acc[nt][3]=b1;
            acc[8+nt][0]=b0; acc[8+nt][1]=b1; acc[8+nt][2]=b0; acc[8+nt][3]=b1;
        }
        #pragma unroll 1
        for(int p=0;p<2;++p){
            // p0: Bhi resident -> Ahi*B and Alo*B.  p1: Blo -> Ahi*B.
            const __nv_bfloat16* src=p? g_Blo : g_Bhi;
            #pragma unroll
            for(int c0=0;c0<2;++c0){
                const char* s=(const char*)src + c0*32768;
                #pragma unroll
                for(int i=0;i<4;++i)
                    cp16(sbB+(uint32_t)(c0*32768+(tid+NTH*i)*16), s+(tid+NTH*i)*16);
                CP_COMMIT();
            }
            #pragma unroll 1
            for(int c=0;c<5;++c){
                if(c<4){ CP_WAIT1(); } else { CP_WAIT0(); }
                __syncthreads();
                const char* bb=Bb+(c&1)*32768;
                if(t0v|t1v){
                    #pragma unroll
                    for(int ksl=0;ksl<4;++ksl){
                        int ks=c*4+ksl;
                        uint2 bfr[8];
                        #pragma unroll
                        for(int nt=0;nt<8;++nt)
                            bfr[nt]=*(const uint2*)(bb+(ksl*32+ncg*8+nt)*256+lane*8);
                        uint4 a0=*(const uint4*)(Ahi+((2*mtp  )*20+ks)*512+lane*16);
                        uint4 a1=*(const uint4*)(Ahi+((2*mtp+1)*20+ks)*512+lane*16);
                        if(t0v){
                            #pragma unroll
                            for(int nt=0;nt<8;++nt) mma16816(acc[nt],a0,bfr[nt]);
                        }
                        if(t1v){
                            #pragma unroll
                            for(int nt=0;nt<8;++nt) mma16816(acc[8+nt],a1,bfr[nt]);
                        }
                        if(p==0){
                            uint4 l0=*(const uint4*)(Alo+((2*mtp  )*20+ks)*512+lane*16);
                            uint4 l1=*(const uint4*)(Alo+((2*mtp+1)*20+ks)*512+lane*16);
                            if(t0v){
                                #pragma unroll
                                for(int nt=0;nt<8;++nt) mma16816(acc[nt],l0,bfr[nt]);
                            }
                            if(t1v){
                                #pragma unroll
                                for(int nt=0;nt<8;++nt) mma16816(acc[8+nt],l1,bfr[nt]);
                            }
                        }
                    }
                }
                __syncthreads();
                if(c<3){
                    const char* s=(const char*)src+(c+2)*32768;
                    #pragma unroll
                    for(int i=0;i<4;++i)
                        cp16(sbB+(uint32_t)((c&1)*32768+(tid+NTH*i)*16), s+(tid+NTH*i)*16);
                    CP_COMMIT();
                }
            }
        }

        // ---- h epilogue: h=tanh(acc) -> A frags (hi/lo); h_final at t=15 ---
        #pragma unroll
        for(int mi=0;mi<2;++mi){
            int mt=2*mtp+mi;
            #pragma unroll
            for(int np=0;np<4;++np){
                float h[8];
                #pragma unroll
                for(int u=0;u<2;++u){
                    int nt=np*2+u;
                    h[u*4+0]=tanh_fast(acc[mi*8+nt][0]);
                    h[u*4+1]=tanh_fast(acc[mi*8+nt][1]);
                    h[u*4+2]=tanh_fast(acc[mi*8+nt][2]);
                    h[u*4+3]=tanh_fast(acc[mi*8+nt][3]);
                }
                uint4 hw,lw;
                split2(h[0],h[1],hw.x,lw.x); split2(h[2],h[3],hw.y,lw.y);
                split2(h[4],h[5],hw.z,lw.z); split2(h[6],h[7],hw.w,lw.w);
                int ks=4+ncg*4+np;
                uint32_t off=(uint32_t)((mt*20+ks)*512+lane*16);
                *(uint4*)(Ahi+off)=hw; *(uint4*)(Alo+off)=lw;
                if(t==T_STEPS-1 && mt<MT){
                    int row=mt*16+(lane>>2), cb=ncg*64+np*16+(lane&3)*2;
                    float* hf=h_final+(size_t)(rowbase+row)*DH;
                    *(float2*)(hf+cb)        =make_float2(h[0],h[1]);
                    *(float2*)(hf+8*DH+cb)   =make_float2(h[2],h[3]);
                    *(float2*)(hf+cb+8)      =make_float2(h[4],h[5]);
                    *(float2*)(hf+8*DH+cb+8) =make_float2(h[6],h[7]);
                }
            }
        }
        __syncthreads();

        // ---- h2o GEMM: D2[rows x 64] over K=256, bf16x3 merged -------------
        {
            #pragma unroll
            for(int i=0;i<4;++i)
                cp16(sbB+(uint32_t)((tid+NTH*i)*16), (const char*)g_Ohi+(tid+NTH*i)*16);
            #pragma unroll
            for(int i=0;i<4;++i)
                cp16(sbB+(uint32_t)(32768+(tid+NTH*i)*16), (const char*)g_Olo+(tid+NTH*i)*16);
            CP_COMMIT(); CP_WAIT0(); __syncthreads();

            float a2[4][4];
            #pragma unroll
            for(int u=0;u<2;++u){
                int col=(ncg*2+u)*8+(lane&3)*2;
                float b0=cs[256+col], b1=cs[256+col+1];
                a2[u][0]=b0;a2[u][1]=b1;a2[u][2]=b0;a2[u][3]=b1;
                a2[2+u][0]=b0;a2[2+u][1]=b1;a2[2+u][2]=b0;a2[2+u][3]=b1;
            }
            if(t0v|t1v){
                #pragma unroll 1
                for(int ks2=0;ks2<16;++ks2){
                    uint2 bh[2], bl[2];
                    #pragma unroll
                    for(int u=0;u<2;++u){
                        bh[u]=*(const uint2*)(Bb+(ks2*8+ncg*2+u)*256+lane*8);
                        bl[u]=*(const uint2*)(Bb+32768+(ks2*8+ncg*2+u)*256+lane*8);
                    }
                    uint4 a0h=*(const uint4*)(Ahi+((2*mtp  )*20+4+ks2)*512+lane*16);
                    uint4 a1h=*(const uint4*)(Ahi+((2*mtp+1)*20+4+ks2)*512+lane*16);
                    uint4 a0l=*(const uint4*)(Alo+((2*mtp  )*20+4+ks2)*512+lane*16);
                    uint4 a1l=*(const uint4*)(Alo+((2*mtp+1)*20+4+ks2)*512+lane*16);
                    if(t0v){
                        #pragma unroll
                        for(int u=0;u<2;++u){
                            mma16816(a2[u],a0h,bh[u]);
                            mma16816(a2[u],a0l,bh[u]);
                            mma16816(a2[u],a0h,bl[u]);
                        }
                    }
                    if(t1v){
                        #pragma unroll
                        for(int u=0;u<2;++u){
                            mma16816(a2[2+u],a1h,bh[u]);
                            mma16816(a2[2+u],a1l,bh[u]);
                            mma16816(a2[2+u],a1h,bl[u]);
                        }
                    }
                }
            }
            __syncthreads();
            // mid = tanh(D2) -> scratch [row][66]
            float* mid=(float*)(sm+OFF_MID);
            #pragma unroll
            for(int mi=0;mi<2;++mi){
                int row=(2*mtp+mi)*16+(lane>>2);
                #pragma unroll
                for(int u=0;u<2;++u){
                    int col=(ncg*2+u)*8+(lane&3)*2, idx=mi*2+u;
                    *(float2*)&mid[row*66+col]=
                        make_float2(tanh_fast(a2[idx][0]),tanh_fast(a2[idx][1]));
                    *(float2*)&mid[(row+8)*66+col]=
                        make_float2(tanh_fast(a2[idx][2]),tanh_fast(a2[idx][3]));
                }
            }
            __syncthreads();
            // fc (guarded rows)
            {
                int row=tid>>2, o=tid&3;
                if(row<nrows){
                    float s=cs[320+o];
                    const float* wf=&cs[324+o*64];
                    const float* mr=&mid[row*66];
                    #pragma unroll
                    for(int m=0;m<64;++m) s+=mr[m]*wf[m];
                    out_seq[((size_t)t*BATCH+rowbase+row)*DOUT+o]=s;
                }
            }
            __syncthreads();
        }
    }
}

// ----------------------------- launch wrapper -------------------------------
extern "C" void kernel_launch(void* const* d_in, const int* in_sizes, int n_in,
                              void* d_out, int out_size){
    const float* x     = (const float*)d_in[0];
    const float* hc1   = (const float*)d_in[1];
    const float* W_i2h = (const float*)d_in[2];
    const float* b_i2h = (const float*)d_in[3];
    const float* W_h2h = (const float*)d_in[4];
    const float* b_h2h = (const float*)d_in[5];
    const float* W_h2o = (const float*)d_in[6];
    const float* b_h2o = (const float*)d_in[7];
    const float* W_fc  = (const float*)d_in[8];
    const float* b_fc  = (const float*)d_in[9];

    float* out=(float*)d_out;
    float* h_final=out+(size_t)T_STEPS*BATCH*DOUT;

    prep<<<(256*320+64*256+255)/256, 256>>>(W_i2h, W_h2h, W_h2o);

    cudaFuncSetAttribute(rnn_mma, cudaFuncAttributeMaxDynamicSharedMemorySize,
                         SMEM_TOTAL);
    rnn_mma<<<GRID, NTH, SMEM_TOTAL>>>(
        x, hc1, b_i2h, b_h2h, b_h2o, W_fc, b_fc, out, h_final);
}